// round 16
// baseline (speedup 1.0000x reference)
#include <cuda_runtime.h>
#include <math.h>

#define EMB    1024
#define NDEC   2048     // WIDTH*MODES*2
#define WIDTH  64
#define MODES  16
#define NH     128      // fc1 hidden
#define MAXB   64
#define KC     16       // K-split chunks in stage A
#define KCHUNK 64       // EMB / KC
#define OT     256      // output-column tile in stage A
#define BH     16       // batches per stage-A block (4-way batch split)
#define NKK    31       // 1 DC + 15 cos + 15 sin
#define TT     64       // t-tile per block in stage C
#define TW     16       // t per warp in stage C
#define NM     15       // MODES-1

typedef unsigned long long u64;

// Scratch (static device globals; no allocation)
__device__ float g_hpart[KC][MAXB * NDEC];   // 8 MB
__device__ float g_coef[MAXB * NKK * NH];    // ~1 MB

// ---- packed f32x2 helpers (sm_100+) --------------------------------------
__device__ __forceinline__ u64 pk2(float lo, float hi) {
    u64 r; asm("mov.b64 %0, {%1, %2};" : "=l"(r) : "f"(lo), "f"(hi)); return r;
}
__device__ __forceinline__ void upk2(u64 v, float& lo, float& hi) {
    asm("mov.b64 {%0, %1}, %2;" : "=f"(lo), "=f"(hi) : "l"(v));
}
__device__ __forceinline__ u64 ffma2(u64 a, u64 b, u64 c) {
    u64 d; asm("fma.rn.f32x2 %0, %1, %2, %3;" : "=l"(d) : "l"(a), "l"(b), "l"(c)); return d;
}
__device__ __forceinline__ u64 fadd2(u64 a, u64 b) {
    u64 d; asm("add.rn.f32x2 %0, %1, %2;" : "=l"(d) : "l"(a), "l"(b)); return d;
}
__device__ __forceinline__ u64 fsub2(u64 a, u64 b) {
    u64 d; asm("sub.rn.f32x2 %0, %1, %2;" : "=l"(d) : "l"(a), "l"(b)); return d;
}
__device__ __forceinline__ u64 fmul2(u64 a, u64 b) {
    u64 d; asm("mul.rn.f32x2 %0, %1, %2;" : "=l"(d) : "l"(a), "l"(b)); return d;
}

// packed gelu with scalar MUFU tanh core:
// gelu(x) = 0.5 x (1 + tanh(sqrt(2/pi)(x + 0.044715 x^3)))
// Packed polynomial/scale ops (fma pipe) around two tanh.approx (MUFU pipe).
// For |x| < 0.1 matches exact erf-gelu to ~1e-6 absolute.
__device__ __forceinline__ u64 gelu2t(u64 x) {
    const u64 K3 = pk2(0.03567740814183429f, 0.03567740814183429f);
    const u64 K1 = pk2(0.7978845608028654f, 0.7978845608028654f);
    const u64 H  = pk2(0.5f, 0.5f);
    u64 x2 = fmul2(x, x);
    u64 t  = ffma2(x2, K3, K1);
    u64 y  = fmul2(t, x);
    float ya, yb; upk2(y, ya, yb);
    float ta, tb;
    asm("tanh.approx.f32 %0, %1;" : "=f"(ta) : "f"(ya));
    asm("tanh.approx.f32 %0, %1;" : "=f"(tb) : "f"(yb));
    u64 th = pk2(ta, tb);
    u64 h  = ffma2(th, H, H);
    return fmul2(x, h);
}

// ---------------------------------------------------------------------------
// Stage A: partial GEMM  h_part[c][b][o] = sum_{e in chunk c} token[b][e]*wdec[e][o]
// grid (NDEC/OT, KC, 4) = 512 blocks. Each block: BH=16 batches as 8 f32x2
// packs in smem. Inner loop processes e-PAIRS: one LDS.128 delivers tok for
// (e, e+1) of a batch-pair -> 8 LDS.128 + 16 FFMA2 + 2 LDG per 2 e's.
// ---------------------------------------------------------------------------
__global__ void __launch_bounds__(OT) stageA(const float* __restrict__ token,
                                             const float* __restrict__ wdec, int B) {
    __shared__ u64 tok2[BH / 2][KCHUNK];
    const int o  = blockIdx.x * OT + threadIdx.x;
    const int k0 = blockIdx.y * KCHUNK;
    const int b0 = blockIdx.z * BH;

    for (int i = threadIdx.x; i < (BH / 2) * KCHUNK; i += OT) {
        int p = i / KCHUNK, e = i % KCHUNK;
        int bb = b0 + 2 * p;
        float v0 = (bb     < B) ? token[(size_t)bb * EMB + k0 + e]       : 0.0f;
        float v1 = (bb + 1 < B) ? token[(size_t)(bb + 1) * EMB + k0 + e] : 0.0f;
        tok2[p][e] = pk2(v0, v1);
    }
    __syncthreads();

    u64 acc[BH / 2];
#pragma unroll
    for (int p = 0; p < BH / 2; p++) acc[p] = 0ULL;

    const float* wp = wdec + (size_t)k0 * NDEC + o;
#pragma unroll 8
    for (int e2 = 0; e2 < KCHUNK; e2 += 2) {
        float wv0 = wp[(size_t)e2 * NDEC];
        float wv1 = wp[(size_t)(e2 + 1) * NDEC];
        u64 w0 = pk2(wv0, wv0);
        u64 w1 = pk2(wv1, wv1);
#pragma unroll
        for (int p = 0; p < BH / 2; p++) {
            ulonglong2 tk = *reinterpret_cast<const ulonglong2*>(&tok2[p][e2]);
            acc[p] = ffma2(tk.x, w0, acc[p]);
            acc[p] = ffma2(tk.y, w1, acc[p]);
        }
    }

    float* dst = g_hpart[blockIdx.y];
#pragma unroll
    for (int p = 0; p < BH / 2; p++) {
        float a, bval; upk2(acc[p], a, bval);
        dst[(size_t)(b0 + 2 * p)     * NDEC + o] = a;
        dst[(size_t)(b0 + 2 * p + 1) * NDEC + o] = bval;
    }
}

// ---------------------------------------------------------------------------
// Stage B: reduce K-split partials + bias, then fold irfft scales + fc1 weight
// into per-batch trig coefficients (h row layout: idx = w*32 + k*2 + {re,im}):
//   Coef[b][0][j]    = (1/L)  * sum_w re[b,w,0] * w1[w,j]        (DC; Im ignored)
//   Coef[b][k][j]    = (2/L)  * sum_w re[b,w,k] * w1[w,j]  k=1..15   (cos)
//   Coef[b][15+k][j] = (-2/L) * sum_w im[b,w,k] * w1[w,j]  k=1..15   (sin)
// ---------------------------------------------------------------------------
__global__ void stageB(const float* __restrict__ w1,
                       const float* __restrict__ bdec, float invL) {
    __shared__ float hs[NDEC];
    __shared__ float w1s[WIDTH * NH];
    const int b = blockIdx.x;
    const int j = threadIdx.x;  // 128 threads

    for (int i = j; i < NDEC; i += NH) {
        float s = bdec[i];
#pragma unroll
        for (int c = 0; c < KC; c++) s += g_hpart[c][b * NDEC + i];
        hs[i] = s;
    }
    for (int i = j; i < WIDTH * NH; i += NH) w1s[i] = w1[i];
    __syncthreads();

    {   // DC term
        float a = 0.0f;
#pragma unroll
        for (int w = 0; w < WIDTH; w++) a += hs[w * 32] * w1s[w * NH + j];
        g_coef[(b * NKK + 0) * NH + j] = a * invL;
    }
#pragma unroll
    for (int k = 1; k < MODES; k++) {
        float ac = 0.0f, as = 0.0f;
#pragma unroll
        for (int w = 0; w < WIDTH; w++) {
            float wv = w1s[w * NH + j];
            ac += hs[w * 32 + k * 2]     * wv;
            as += hs[w * 32 + k * 2 + 1] * wv;
        }
        g_coef[(b * NKK + k)      * NH + j] = ac * (2.0f * invL);
        g_coef[(b * NKK + 15 + k) * NH + j] = as * (-2.0f * invL);
    }
}

// ---------------------------------------------------------------------------
// Stage C: quarter-wave. grid (L/4/TT + 1, B), 128 threads, 3 blocks/SM.
// Each warp owns TW=16 t in [0, L/4]; mode-parity-split accumulators give 4
// outputs per m-loop. base (coef0 + b1) folded into even-cos accumulator init:
//   pre(t)     = u + (Se+So)    pre(L-t)   = u - (Se+So)
//   pre(L/2-t) = v - (Se-So)    pre(L/2+t) = v + (Se-So)
// Epilogue: PACKED gelu2t (packed poly + scalar MUFU tanh), packed w2 dots,
// 4 INTERLEAVED butterflies (no redux.f32 on sm_103 — R11; serial reduce
// slower — R9). Stores from lane 0; seam duplicates deterministic.
// ---------------------------------------------------------------------------
__global__ void __launch_bounds__(NH, 3) stageC(
        const float* __restrict__ b1, const float* __restrict__ w2,
        const float* __restrict__ b2, float* __restrict__ out,
        float omega, int TL, int L, int lmask) {
    __shared__ ulonglong2 tab[4 * TW * NM];   // [warp][tl][m] = {(c,c),(s,s)}
    __shared__ float cfs[NKK * NH];           // coef slab for this batch
    __shared__ float b1s[NH], w2s[NH];

    const int b    = blockIdx.y;
    const int j    = threadIdx.x;
    const int warp = j >> 5, lane = j & 31;
    const int tw0  = blockIdx.x * TT + warp * TW;   // this warp's first t
    const int quarterL = L >> 2;
    const int halfL    = L >> 1;

    // stage coef slab + b1 + w2 into smem
    {
        const float4* src = (const float4*)(g_coef + (size_t)b * NKK * NH);
        float4* dstv = (float4*)cfs;
        for (int i = j; i < (NKK * NH) / 4; i += NH) dstv[i] = src[i];
        b1s[j] = b1[j];
        w2s[j] = w2[j];
    }

    // fill warp-private trig table (exact integer angle reduction + __sincosf)
    ulonglong2* mytab = tab + warp * TW * NM;
    for (int i = lane; i < TW * NM; i += 32) {
        int tl = i / NM, m = i - tl * NM;
        int v  = (m + 1) * (tw0 + tl);
        int r  = (lmask >= 0) ? (v & lmask) : (v % L);
        float ang = omega * (float)r;
        float s, c;
        __sincosf(ang, &s, &c);
        mytab[i] = make_ulonglong2(pk2(c, c), pk2(s, s));
    }
    __syncthreads();

    // per-thread coefficients: j0..j3 = lane, lane+32, lane+64, lane+96
    const int j0 = lane, j1 = lane + 32, j2 = lane + 64, j3 = lane + 96;
    const u64 base01 = pk2(cfs[j0] + b1s[j0], cfs[j1] + b1s[j1]);
    const u64 base23 = pk2(cfs[j2] + b1s[j2], cfs[j3] + b1s[j3]);
    u64 cc01[NM], cc23[NM], sv01[NM], sv23[NM];
#pragma unroll
    for (int m = 0; m < NM; m++) {
        const float* p = cfs + (1 + m) * NH;
        cc01[m] = pk2(p[j0], p[j1]);
        cc23[m] = pk2(p[j2], p[j3]);
        const float* q = cfs + (16 + m) * NH;
        sv01[m] = pk2(q[j0], q[j1]);
        sv23[m] = pk2(q[j2], q[j3]);
    }
    const u64 w2_01 = pk2(w2s[j0], w2s[j1]);
    const u64 w2_23 = pk2(w2s[j2], w2s[j3]);
    const float b2v = b2[0];

    for (int tl = 0; tl < TW; tl++) {
        const int t = tw0 + tl;
        if (t > quarterL) break;

        // parity-split accumulation; base folded into even-cos init.
        u64 ae01 = base01, ao01 = 0, se01 = 0, so01 = 0;
        u64 ae23 = base23, ao23 = 0, se23 = 0, so23 = 0;
        const ulonglong2* tp = mytab + tl * NM;
#pragma unroll
        for (int m = 0; m < NM; m++) {
            ulonglong2 q = tp[m];
            if (m & 1) {   // mode even
                ae01 = ffma2(cc01[m], q.x, ae01);
                ae23 = ffma2(cc23[m], q.x, ae23);
                se01 = ffma2(sv01[m], q.y, se01);
                se23 = ffma2(sv23[m], q.y, se23);
            } else {       // mode odd
                ao01 = ffma2(cc01[m], q.x, ao01);
                ao23 = ffma2(cc23[m], q.x, ao23);
                so01 = ffma2(sv01[m], q.y, so01);
                so23 = ffma2(sv23[m], q.y, so23);
            }
        }

        // combine into the 4 pre-activation packs (base already inside ae)
        u64 u01 = fadd2(ae01, ao01), v01 = fsub2(ae01, ao01);
        u64 p01 = fadd2(se01, so01), q01 = fsub2(se01, so01);
        u64 u23 = fadd2(ae23, ao23), v23 = fsub2(ae23, ao23);
        u64 p23 = fadd2(se23, so23), q23 = fsub2(se23, so23);

        float r0, r1, r2, r3;
        {   // output t : u + p
            u64 g01 = gelu2t(fadd2(u01, p01));
            u64 g23 = gelu2t(fadd2(u23, p23));
            u64 acc = ffma2(g01, w2_01, fmul2(g23, w2_23));
            float xa, xb; upk2(acc, xa, xb); r0 = xa + xb;
        }
        {   // output L - t : u - p
            u64 g01 = gelu2t(fsub2(u01, p01));
            u64 g23 = gelu2t(fsub2(u23, p23));
            u64 acc = ffma2(g01, w2_01, fmul2(g23, w2_23));
            float xa, xb; upk2(acc, xa, xb); r1 = xa + xb;
        }
        {   // output L/2 - t : v - q
            u64 g01 = gelu2t(fsub2(v01, q01));
            u64 g23 = gelu2t(fsub2(v23, q23));
            u64 acc = ffma2(g01, w2_01, fmul2(g23, w2_23));
            float xa, xb; upk2(acc, xa, xb); r2 = xa + xb;
        }
        {   // output L/2 + t : v + q
            u64 g01 = gelu2t(fadd2(v01, q01));
            u64 g23 = gelu2t(fadd2(v23, q23));
            u64 acc = ffma2(g01, w2_01, fmul2(g23, w2_23));
            float xa, xb; upk2(acc, xa, xb); r3 = xa + xb;
        }

        // 4 interleaved butterfly reductions (independent latency chains)
#pragma unroll
        for (int off = 16; off; off >>= 1) {
            r0 += __shfl_xor_sync(0xffffffffu, r0, off);
            r1 += __shfl_xor_sync(0xffffffffu, r1, off);
            r2 += __shfl_xor_sync(0xffffffffu, r2, off);
            r3 += __shfl_xor_sync(0xffffffffu, r3, off);
        }

        if (lane == 0) {
            float* ob = out + (size_t)b * TL;
            ob[t] = r0 + b2v;                               // t <= L/4 < TL
            int i1 = L - t;
            if (i1 < TL) ob[i1] = r1 + b2v;                 // (3L/4, L)
            ob[halfL - t] = r2 + b2v;                       // [L/4, L/2]
            ob[halfL + t] = r3 + b2v;                       // [L/2, 3L/4]
        }
    }
}

// ---------------------------------------------------------------------------
extern "C" void kernel_launch(void* const* d_in, const int* in_sizes, int n_in,
                              void* d_out, int out_size) {
    // inputs: token, [x_len], w_dec, b_dec, w1, b1, w2, b2
    const int off = (n_in == 8) ? 1 : 0;
    const float* token = (const float*)d_in[0];
    const float* wdec  = (const float*)d_in[1 + off];
    const float* bdec  = (const float*)d_in[2 + off];
    const float* w1    = (const float*)d_in[3 + off];
    const float* b1    = (const float*)d_in[4 + off];
    const float* w2    = (const float*)d_in[5 + off];
    const float* b2    = (const float*)d_in[6 + off];
    float* out = (float*)d_out;

    int B  = in_sizes[0] / EMB;         // 64
    int TL = out_size / B;              // L - 2 = 8190
    int L  = TL + 2;                    // 8192
    float invL  = 1.0f / (float)L;
    float omega = (float)(2.0 * 3.14159265358979323846 / (double)L);
    int lmask = ((L & (L - 1)) == 0) ? (L - 1) : -1;

    stageA<<<dim3(NDEC / OT, KC, 4), OT>>>(token, wdec, B);

    stageB<<<B, NH>>>(w1, bdec, invL);

    int gx = (L / 4) / TT + 1;          // covers t in [0, L/4] (+ guard tile)
    stageC<<<dim3(gx, B), NH>>>(b1, w2, b2, out, omega, TL, L, lmask);
}

// round 17
// speedup vs baseline: 1.0419x; 1.0419x over previous
#include <cuda_runtime.h>
#include <math.h>

#define EMB    1024
#define NDEC   2048     // WIDTH*MODES*2
#define WIDTH  64
#define MODES  16
#define NH     128      // fc1 hidden
#define MAXB   64
#define KC     32       // K-split chunks in stage A
#define KCHUNK 32       // EMB / KC
#define OT     256      // threads in stage A (each owns 2 output columns)
#define BH     16       // batches per stage-A block (4-way batch split)
#define NKK    31       // 1 DC + 15 cos + 15 sin
#define TT     64       // t-tile per block in stage C
#define TW     16       // t per warp in stage C
#define NM     15       // MODES-1

typedef unsigned long long u64;

// Scratch (static device globals; no allocation)
__device__ float g_hpart[KC][MAXB * NDEC];   // 16 MB
__device__ float g_coef[MAXB * NKK * NH];    // ~1 MB

// ---- packed f32x2 helpers (sm_100+) --------------------------------------
__device__ __forceinline__ u64 pk2(float lo, float hi) {
    u64 r; asm("mov.b64 %0, {%1, %2};" : "=l"(r) : "f"(lo), "f"(hi)); return r;
}
__device__ __forceinline__ void upk2(u64 v, float& lo, float& hi) {
    asm("mov.b64 {%0, %1}, %2;" : "=f"(lo), "=f"(hi) : "l"(v));
}
__device__ __forceinline__ u64 ffma2(u64 a, u64 b, u64 c) {
    u64 d; asm("fma.rn.f32x2 %0, %1, %2, %3;" : "=l"(d) : "l"(a), "l"(b), "l"(c)); return d;
}
__device__ __forceinline__ u64 fadd2(u64 a, u64 b) {
    u64 d; asm("add.rn.f32x2 %0, %1, %2;" : "=l"(d) : "l"(a), "l"(b)); return d;
}
__device__ __forceinline__ u64 fsub2(u64 a, u64 b) {
    u64 d; asm("sub.rn.f32x2 %0, %1, %2;" : "=l"(d) : "l"(a), "l"(b)); return d;
}

// gelu via HW tanh.approx (MUFU pipe — off the saturated fma pipe). Scalar
// form (R16 showed packed tanh wrapper's movs eat the gains).
// gelu(x) = 0.5 x (1 + tanh( sqrt(2/pi) (x + 0.044715 x^3) ))
// For |x| < 0.1 matches exact erf-gelu to ~1e-6 absolute.
__device__ __forceinline__ float gelu_t(float x) {
    float x2 = x * x;
    float t  = fmaf(x2, 0.03567740814183429f, 0.7978845608028654f);
    float y  = t * x;
    float th;
    asm("tanh.approx.f32 %0, %1;" : "=f"(th) : "f"(y));
    float h  = fmaf(th, 0.5f, 0.5f);
    return x * h;
}

// ---------------------------------------------------------------------------
// Stage A: partial GEMM  h_part[c][b][o] = sum_{e in chunk c} token[b][e]*wdec[e][o]
// grid (NDEC/(2*OT), KC, 4) = (4, 32, 4) = 512 blocks. Each thread owns TWO
// adjacent output columns (o, o+1): one coalesced LDG.64 of wdec per e feeds
// 16 FFMA2 (8 batch-packs x 2 columns). Stores are STG.64.
// ---------------------------------------------------------------------------
__global__ void __launch_bounds__(OT) stageA(const float* __restrict__ token,
                                             const float* __restrict__ wdec, int B) {
    __shared__ u64 tok2[BH / 2][KCHUNK];
    const int o  = blockIdx.x * (OT * 2) + threadIdx.x * 2;
    const int k0 = blockIdx.y * KCHUNK;
    const int b0 = blockIdx.z * BH;

    {   // 256 entries, exactly one per thread
        int i = threadIdx.x;
        int p = i / KCHUNK, e = i % KCHUNK;
        int bb = b0 + 2 * p;
        float v0 = (bb     < B) ? token[(size_t)bb * EMB + k0 + e]       : 0.0f;
        float v1 = (bb + 1 < B) ? token[(size_t)(bb + 1) * EMB + k0 + e] : 0.0f;
        tok2[p][e] = pk2(v0, v1);
    }
    __syncthreads();

    u64 acc0[BH / 2], acc1[BH / 2];
#pragma unroll
    for (int p = 0; p < BH / 2; p++) { acc0[p] = 0ULL; acc1[p] = 0ULL; }

    const float2* wp2 = (const float2*)(wdec + (size_t)k0 * NDEC + o);
#pragma unroll 8
    for (int e = 0; e < KCHUNK; e++) {
        float2 wv = wp2[(size_t)e * (NDEC / 2)];
        u64 wa = pk2(wv.x, wv.x);
        u64 wb = pk2(wv.y, wv.y);
#pragma unroll
        for (int p = 0; p < BH / 2; p++) {
            u64 tk = tok2[p][e];
            acc0[p] = ffma2(tk, wa, acc0[p]);
            acc1[p] = ffma2(tk, wb, acc1[p]);
        }
    }

    float* dst = g_hpart[blockIdx.y];
#pragma unroll
    for (int p = 0; p < BH / 2; p++) {
        float a0, c0, a1, c1;
        upk2(acc0[p], a0, c0);   // a0: batch b0+2p col o ; c0: batch b0+2p+1 col o
        upk2(acc1[p], a1, c1);   // a1: batch b0+2p col o+1 ; c1: batch b0+2p+1 col o+1
        *reinterpret_cast<float2*>(&dst[(size_t)(b0 + 2 * p)     * NDEC + o]) = make_float2(a0, a1);
        *reinterpret_cast<float2*>(&dst[(size_t)(b0 + 2 * p + 1) * NDEC + o]) = make_float2(c0, c1);
    }
}

// ---------------------------------------------------------------------------
// Stage B: reduce K-split partials + bias, then fold irfft scales + fc1 weight
// into per-batch trig coefficients (h row layout: idx = w*32 + k*2 + {re,im}):
//   Coef[b][0][j]    = (1/L)  * sum_w re[b,w,0] * w1[w,j]        (DC; Im ignored)
//   Coef[b][k][j]    = (2/L)  * sum_w re[b,w,k] * w1[w,j]  k=1..15   (cos)
//   Coef[b][15+k][j] = (-2/L) * sum_w im[b,w,k] * w1[w,j]  k=1..15   (sin)
// ---------------------------------------------------------------------------
__global__ void stageB(const float* __restrict__ w1,
                       const float* __restrict__ bdec, float invL) {
    __shared__ float hs[NDEC];
    __shared__ float w1s[WIDTH * NH];
    const int b = blockIdx.x;
    const int j = threadIdx.x;  // 128 threads

    for (int i = j; i < NDEC; i += NH) {
        float s = bdec[i];
#pragma unroll
        for (int c = 0; c < KC; c++) s += g_hpart[c][b * NDEC + i];
        hs[i] = s;
    }
    for (int i = j; i < WIDTH * NH; i += NH) w1s[i] = w1[i];
    __syncthreads();

    {   // DC term
        float a = 0.0f;
#pragma unroll
        for (int w = 0; w < WIDTH; w++) a += hs[w * 32] * w1s[w * NH + j];
        g_coef[(b * NKK + 0) * NH + j] = a * invL;
    }
#pragma unroll
    for (int k = 1; k < MODES; k++) {
        float ac = 0.0f, as = 0.0f;
#pragma unroll
        for (int w = 0; w < WIDTH; w++) {
            float wv = w1s[w * NH + j];
            ac += hs[w * 32 + k * 2]     * wv;
            as += hs[w * 32 + k * 2 + 1] * wv;
        }
        g_coef[(b * NKK + k)      * NH + j] = ac * (2.0f * invL);
        g_coef[(b * NKK + 15 + k) * NH + j] = as * (-2.0f * invL);
    }
}

// ---------------------------------------------------------------------------
// Stage C: quarter-wave. grid (L/4/TT + 1, B), 128 threads, 3 blocks/SM.
// Exact R14 form (best measured: 71us). Each warp owns TW=16 t in [0, L/4];
// mode-parity-split accumulators give 4 outputs per m-loop; base folded into
// even-cos accumulator init:
//   pre(t)     = u + (Se+So)    pre(L-t)   = u - (Se+So)
//   pre(L/2-t) = v - (Se-So)    pre(L/2+t) = v + (Se-So)
// Scalar MUFU-tanh gelu, scalar w2 dots, 4 INTERLEAVED butterflies (no
// redux.f32 on sm_103 — R11; serial reduce slower — R9; packed tanh wrapper
// slower — R16). Stores from lane 0; seam duplicates deterministic.
// ---------------------------------------------------------------------------
__global__ void __launch_bounds__(NH, 3) stageC(
        const float* __restrict__ b1, const float* __restrict__ w2,
        const float* __restrict__ b2, float* __restrict__ out,
        float omega, int TL, int L, int lmask) {
    __shared__ ulonglong2 tab[4 * TW * NM];   // [warp][tl][m] = {(c,c),(s,s)}
    __shared__ float cfs[NKK * NH];           // coef slab for this batch
    __shared__ float b1s[NH], w2s[NH];

    const int b    = blockIdx.y;
    const int j    = threadIdx.x;
    const int warp = j >> 5, lane = j & 31;
    const int tw0  = blockIdx.x * TT + warp * TW;   // this warp's first t
    const int quarterL = L >> 2;
    const int halfL    = L >> 1;

    // stage coef slab + b1 + w2 into smem
    {
        const float4* src = (const float4*)(g_coef + (size_t)b * NKK * NH);
        float4* dstv = (float4*)cfs;
        for (int i = j; i < (NKK * NH) / 4; i += NH) dstv[i] = src[i];
        b1s[j] = b1[j];
        w2s[j] = w2[j];
    }

    // fill warp-private trig table (exact integer angle reduction + __sincosf)
    ulonglong2* mytab = tab + warp * TW * NM;
    for (int i = lane; i < TW * NM; i += 32) {
        int tl = i / NM, m = i - tl * NM;
        int v  = (m + 1) * (tw0 + tl);
        int r  = (lmask >= 0) ? (v & lmask) : (v % L);
        float ang = omega * (float)r;
        float s, c;
        __sincosf(ang, &s, &c);
        mytab[i] = make_ulonglong2(pk2(c, c), pk2(s, s));
    }
    __syncthreads();

    // per-thread coefficients: j0..j3 = lane, lane+32, lane+64, lane+96
    const int j0 = lane, j1 = lane + 32, j2 = lane + 64, j3 = lane + 96;
    const u64 base01 = pk2(cfs[j0] + b1s[j0], cfs[j1] + b1s[j1]);
    const u64 base23 = pk2(cfs[j2] + b1s[j2], cfs[j3] + b1s[j3]);
    u64 cc01[NM], cc23[NM], sv01[NM], sv23[NM];
#pragma unroll
    for (int m = 0; m < NM; m++) {
        const float* p = cfs + (1 + m) * NH;
        cc01[m] = pk2(p[j0], p[j1]);
        cc23[m] = pk2(p[j2], p[j3]);
        const float* q = cfs + (16 + m) * NH;
        sv01[m] = pk2(q[j0], q[j1]);
        sv23[m] = pk2(q[j2], q[j3]);
    }
    const float w20 = w2s[j0], w21 = w2s[j1], w22 = w2s[j2], w23 = w2s[j3];
    const float b2v = b2[0];

    for (int tl = 0; tl < TW; tl++) {
        const int t = tw0 + tl;
        if (t > quarterL) break;

        // parity-split accumulation; base folded into even-cos init.
        u64 ae01 = base01, ao01 = 0, se01 = 0, so01 = 0;
        u64 ae23 = base23, ao23 = 0, se23 = 0, so23 = 0;
        const ulonglong2* tp = mytab + tl * NM;
#pragma unroll
        for (int m = 0; m < NM; m++) {
            ulonglong2 q = tp[m];
            if (m & 1) {   // mode even
                ae01 = ffma2(cc01[m], q.x, ae01);
                ae23 = ffma2(cc23[m], q.x, ae23);
                se01 = ffma2(sv01[m], q.y, se01);
                se23 = ffma2(sv23[m], q.y, se23);
            } else {       // mode odd
                ao01 = ffma2(cc01[m], q.x, ao01);
                ao23 = ffma2(cc23[m], q.x, ao23);
                so01 = ffma2(sv01[m], q.y, so01);
                so23 = ffma2(sv23[m], q.y, so23);
            }
        }

        // combine into the 4 pre-activation packs (base already inside ae)
        u64 u01 = fadd2(ae01, ao01), v01 = fsub2(ae01, ao01);
        u64 p01 = fadd2(se01, so01), q01 = fsub2(se01, so01);
        u64 u23 = fadd2(ae23, ao23), v23 = fsub2(ae23, ao23);
        u64 p23 = fadd2(se23, so23), q23 = fsub2(se23, so23);

        float r0, r1, r2, r3;
        {   // output t : u + p
            float x0, x1, x2, x3;
            upk2(fadd2(u01, p01), x0, x1);
            upk2(fadd2(u23, p23), x2, x3);
            r0 = gelu_t(x0) * w20;
            r0 = fmaf(gelu_t(x1), w21, r0);
            r0 = fmaf(gelu_t(x2), w22, r0);
            r0 = fmaf(gelu_t(x3), w23, r0);
        }
        {   // output L - t : u - p
            float x0, x1, x2, x3;
            upk2(fsub2(u01, p01), x0, x1);
            upk2(fsub2(u23, p23), x2, x3);
            r1 = gelu_t(x0) * w20;
            r1 = fmaf(gelu_t(x1), w21, r1);
            r1 = fmaf(gelu_t(x2), w22, r1);
            r1 = fmaf(gelu_t(x3), w23, r1);
        }
        {   // output L/2 - t : v - q
            float x0, x1, x2, x3;
            upk2(fsub2(v01, q01), x0, x1);
            upk2(fsub2(v23, q23), x2, x3);
            r2 = gelu_t(x0) * w20;
            r2 = fmaf(gelu_t(x1), w21, r2);
            r2 = fmaf(gelu_t(x2), w22, r2);
            r2 = fmaf(gelu_t(x3), w23, r2);
        }
        {   // output L/2 + t : v + q
            float x0, x1, x2, x3;
            upk2(fadd2(v01, q01), x0, x1);
            upk2(fadd2(v23, q23), x2, x3);
            r3 = gelu_t(x0) * w20;
            r3 = fmaf(gelu_t(x1), w21, r3);
            r3 = fmaf(gelu_t(x2), w22, r3);
            r3 = fmaf(gelu_t(x3), w23, r3);
        }

        // 4 interleaved butterfly reductions (independent latency chains)
#pragma unroll
        for (int off = 16; off; off >>= 1) {
            r0 += __shfl_xor_sync(0xffffffffu, r0, off);
            r1 += __shfl_xor_sync(0xffffffffu, r1, off);
            r2 += __shfl_xor_sync(0xffffffffu, r2, off);
            r3 += __shfl_xor_sync(0xffffffffu, r3, off);
        }

        if (lane == 0) {
            float* ob = out + (size_t)b * TL;
            ob[t] = r0 + b2v;                               // t <= L/4 < TL
            int i1 = L - t;
            if (i1 < TL) ob[i1] = r1 + b2v;                 // (3L/4, L)
            ob[halfL - t] = r2 + b2v;                       // [L/4, L/2]
            ob[halfL + t] = r3 + b2v;                       // [L/2, 3L/4]
        }
    }
}

// ---------------------------------------------------------------------------
extern "C" void kernel_launch(void* const* d_in, const int* in_sizes, int n_in,
                              void* d_out, int out_size) {
    // inputs: token, [x_len], w_dec, b_dec, w1, b1, w2, b2
    const int off = (n_in == 8) ? 1 : 0;
    const float* token = (const float*)d_in[0];
    const float* wdec  = (const float*)d_in[1 + off];
    const float* bdec  = (const float*)d_in[2 + off];
    const float* w1    = (const float*)d_in[3 + off];
    const float* b1    = (const float*)d_in[4 + off];
    const float* w2    = (const float*)d_in[5 + off];
    const float* b2    = (const float*)d_in[6 + off];
    float* out = (float*)d_out;

    int B  = in_sizes[0] / EMB;         // 64
    int TL = out_size / B;              // L - 2 = 8190
    int L  = TL + 2;                    // 8192
    float invL  = 1.0f / (float)L;
    float omega = (float)(2.0 * 3.14159265358979323846 / (double)L);
    int lmask = ((L & (L - 1)) == 0) ? (L - 1) : -1;

    stageA<<<dim3(NDEC / (OT * 2), KC, 4), OT>>>(token, wdec, B);

    stageB<<<B, NH>>>(w1, bdec, invL);

    int gx = (L / 4) / TT + 1;          // covers t in [0, L/4] (+ guard tile)
    stageC<<<dim3(gx, B), NH>>>(b1, w2, b2, out, omega, TL, L, lmask);
}